// round 16
// baseline (speedup 1.0000x reference)
#include <cuda_runtime.h>
#include <cstdint>
#include <cstddef>

// ============================================================================
// ROI classifier head = 3-layer MLP (grouping by image id is an identity perm
// on rows, so batch_indices is unused).
//   C1 = relu(X @ W1 + b1)   [2048,12544]x[12544,1024]
//   C2 = relu(C1 @ W2 + b2)  [2048,1024]x[1024,1024]
//   out = C2 @ Wc + bc       [2048,1024]x[1024,81]
//
// R9: toolchain targets compute_103 (non-'a') => NO tcgen05. Ampere-style
// mma.sync.m16n8k8 TF32 GEMM (baseline PTX only): cp.async 4-stage pipeline,
// ldmatrix fragment loads from SW128-swizzled SMEM, register accumulators.
// All operands RNA-rounded to tf32 (eps~4.9e-4) so three chained layers stay
// under the 1e-3 threshold.
// R10-R16: fragment-layout, pipeline, launch-path, capture, swizzle-range,
// and ldmatrix address-supply audits; no changes.
// ============================================================================

#define SWZ(off) ((off) ^ (((off) >> 3) & 0x70))

__device__ __forceinline__ uint32_t smem_u32(const void* p) {
    uint32_t a;
    asm("{ .reg .u64 t; cvta.to.shared.u64 t, %1; cvt.u32.u64 %0, t; }"
        : "=r"(a) : "l"(p));
    return a;
}

__device__ __forceinline__ float to_tf32(float x) {
    float r;
    asm("cvt.rna.tf32.f32 %0, %1;" : "=f"(r) : "f"(x));
    return r;
}

__device__ __forceinline__ void cp16(uint32_t s, const void* g) {
    asm volatile("cp.async.cg.shared.global [%0], [%1], 16;" :: "r"(s), "l"(g));
}

__device__ __forceinline__ void ldm4(uint32_t r[4], uint32_t addr) {
    asm volatile("ldmatrix.sync.aligned.m8n8.x4.shared.b16 {%0,%1,%2,%3}, [%4];"
                 : "=r"(r[0]), "=r"(r[1]), "=r"(r[2]), "=r"(r[3]) : "r"(addr));
}

__device__ __forceinline__ void mma_tf32(float d[4], const uint32_t a[4],
                                         uint32_t b0, uint32_t b1) {
    asm volatile(
        "mma.sync.aligned.m16n8k8.row.col.f32.tf32.tf32.f32 "
        "{%0,%1,%2,%3}, {%4,%5,%6,%7}, {%8,%9}, {%0,%1,%2,%3};"
        : "+f"(d[0]), "+f"(d[1]), "+f"(d[2]), "+f"(d[3])
        : "r"(a[0]), "r"(a[1]), "r"(a[2]), "r"(a[3]), "r"(b0), "r"(b1));
}

// ---------------------------------------------------------------------------
// Problem sizes
// ---------------------------------------------------------------------------
static constexpr int N_ROWS   = 2048;
static constexpr int FEAT_DIM = 12544;
static constexpr int HID      = 1024;
static constexpr int NCLS     = 81;
static constexpr int NCLS_PAD = 128;

// GEMM tiling
static constexpr int MT = 128, NT = 128, KT = 32, STAGES = 4;
static constexpr int TILE_BYTES  = MT * KT * 4;           // 16 KB per operand
static constexpr int STAGE_BYTES = 2 * TILE_BYTES;        // 32 KB (A+B)
static constexpr int SMEM_TILES_OFF = 1024;
static constexpr int GEMM_SMEM = SMEM_TILES_OFF + STAGES * STAGE_BYTES; // 132096

// ---------------------------------------------------------------------------
// Scratch (static __device__ — runtime allocation is forbidden)
// ---------------------------------------------------------------------------
__device__ __align__(1024) float g_Xr[N_ROWS * FEAT_DIM];     // rounded features
__device__ __align__(1024) float g_W1T[HID * FEAT_DIM];       // W1^T, rounded
__device__ __align__(1024) float g_W2T[HID * HID];            // W2^T, rounded
__device__ __align__(1024) float g_WcT[NCLS_PAD * HID];       // Wc^T, zero-pad
__device__ __align__(1024) float g_C1[N_ROWS * HID];
__device__ __align__(1024) float g_C2[N_ROWS * HID];

// ---------------------------------------------------------------------------
// Prep kernels
// ---------------------------------------------------------------------------
__global__ void round_tf32_kernel(const float4* __restrict__ in,
                                  float4* __restrict__ out, int n4) {
    for (int i = blockIdx.x * blockDim.x + threadIdx.x; i < n4;
         i += gridDim.x * blockDim.x) {
        float4 v = in[i];
        v.x = to_tf32(v.x); v.y = to_tf32(v.y);
        v.z = to_tf32(v.z); v.w = to_tf32(v.w);
        out[i] = v;
    }
}

// in: [K][N] row-major -> out: [NOUT][K] row-major (rows n>=N zero), rounded.
__global__ void transpose_round_kernel(const float* __restrict__ in,
                                       float* __restrict__ out,
                                       int K, int N, int NOUT) {
    __shared__ float tile[32][33];
    int k0 = blockIdx.x * 32, n0 = blockIdx.y * 32;
    int x = threadIdx.x, y = threadIdx.y;
    #pragma unroll
    for (int i = y; i < 32; i += 8) {
        int n = n0 + x;
        float v = 0.f;
        if (n < N) v = in[(size_t)(k0 + i) * N + n];
        tile[i][x] = to_tf32(v);
    }
    __syncthreads();
    #pragma unroll
    for (int i = y; i < 32; i += 8) {
        int n = n0 + i;
        if (n < NOUT) out[(size_t)n * K + k0 + x] = tile[x][i];
    }
}

// ---------------------------------------------------------------------------
// TF32 GEMM: C[m,n] = act(sum_k A[m,k]*B[n,k] + bias[n])
//   A: [gridDim.y*128, K] K-major,  B: [gridDim.x*128, K] K-major
// 256 threads = 8 warps (2 m x 4 n), warp tile 64x32, mma.m16n8k8.
// ---------------------------------------------------------------------------
__device__ __forceinline__ void load_stage(const float* __restrict__ A,
                                           const float* __restrict__ B,
                                           int K, int m0, int n0, uint32_t sb,
                                           int it, int tid) {
    const uint32_t st = sb + SMEM_TILES_OFF + (uint32_t)(it & (STAGES - 1)) * STAGE_BYTES;
    const int koff = it * KT;
    #pragma unroll
    for (int c = 0; c < 4; c++) {
        int idx = c * 256 + tid;          // 1024 16B-chunks per operand tile
        int row = idx >> 3, cin = idx & 7;
        uint32_t off = (uint32_t)row * 128 + (uint32_t)((cin * 16) ^ ((row & 7) << 4));
        cp16(st + off,              A + (size_t)(m0 + row) * K + koff + cin * 4);
        cp16(st + TILE_BYTES + off, B + (size_t)(n0 + row) * K + koff + cin * 4);
    }
    asm volatile("cp.async.commit_group;" ::: "memory");
}

__global__ void __launch_bounds__(256, 1)
gemm_tf32_kernel(const float* __restrict__ A, const float* __restrict__ B,
                 const float* __restrict__ bias, float* __restrict__ C,
                 int K, int ldc, int nvalid, int nbias, int relu_round) {
    extern __shared__ __align__(1024) char smem[];
    const uint32_t sb = smem_u32(smem);
    const int tid = threadIdx.x, wid = tid >> 5, l = tid & 31;
    const int wm = wid >> 2, wn = wid & 3;       // warp grid 2 x 4
    const int m0 = blockIdx.y * MT, n0 = blockIdx.x * NT;
    const int NITER = K / KT;

    // Bias staged to smem [64 .. 576)
    if (tid < NT) {
        float bv = 0.f;
        if (n0 + tid < nbias) bv = bias[n0 + tid];
        ((float*)(smem + 64))[tid] = bv;
    }

    // ldmatrix per-lane addressing (PTX m16n8k8 fragment layouts):
    //   x4 submatrix s = l/8, row-in-submatrix rr = l%8
    // A submatrices (0,0),(8,0),(0,+16B),(8,+16B); B: (0,0),(0,+16B),(8,0),(8,+16B)
    const int s = l >> 3, rr = l & 7;
    const int arow_off = (s & 1) * 8 + rr;
    const uint32_t abyte = (uint32_t)((s >> 1) * 16);
    const int brow_off = (s >> 1) * 8 + rr;
    const uint32_t bbyte = (uint32_t)((s & 1) * 16);
    const uint32_t cx = (uint32_t)(rr << 4);     // SW128: chunk ^= row%8

    float acc[4][4][4];
    #pragma unroll
    for (int mi = 0; mi < 4; mi++)
        #pragma unroll
        for (int ni = 0; ni < 4; ni++)
            #pragma unroll
            for (int j = 0; j < 4; j++) acc[mi][ni][j] = 0.f;

    // Prologue: STAGES-1 stages in flight
    for (int j = 0; j < STAGES - 1 && j < NITER; j++)
        load_stage(A, B, K, m0, n0, sb, j, tid);

    for (int it = 0; it < NITER; ++it) {
        // Expose stage `it`: groups committed so far = min(3+it, NITER);
        // allowed pending = min(2, NITER-1-it) (2 steady-state, 1/0 in tail).
        int pend = NITER - 1 - it;
        if (pend >= 2)      asm volatile("cp.async.wait_group 2;" ::: "memory");
        else if (pend == 1) asm volatile("cp.async.wait_group 1;" ::: "memory");
        else                asm volatile("cp.async.wait_group 0;" ::: "memory");
        __syncthreads();   // all warps done reading buffer (it-1)%4

        if (it + (STAGES - 1) < NITER)
            load_stage(A, B, K, m0, n0, sb, it + STAGES - 1, tid);

        const uint32_t Ab = sb + SMEM_TILES_OFF + (uint32_t)(it & 3) * STAGE_BYTES;
        const uint32_t Bb = Ab + TILE_BYTES;
        uint32_t aR[4], bR[2];
        #pragma unroll
        for (int mi = 0; mi < 4; mi++)
            aR[mi] = Ab + (uint32_t)(wm * 64 + mi * 16 + arow_off) * 128;
        #pragma unroll
        for (int p = 0; p < 2; p++)
            bR[p] = Bb + (uint32_t)(wn * 32 + p * 16 + brow_off) * 128;

        #pragma unroll
        for (int kk = 0; kk < 4; kk++) {      // 4 x k8 per 32-wide K tile
            const uint32_t kb = (uint32_t)(kk * 32);
            uint32_t a[4][4], b[2][4];
            #pragma unroll
            for (int mi = 0; mi < 4; mi++)
                ldm4(a[mi], aR[mi] + ((kb + abyte) ^ cx));
            #pragma unroll
            for (int p = 0; p < 2; p++)
                ldm4(b[p], bR[p] + ((kb + bbyte) ^ cx));
            #pragma unroll
            for (int mi = 0; mi < 4; mi++)
                #pragma unroll
                for (int ni = 0; ni < 4; ni++)
                    mma_tf32(acc[mi][ni], a[mi],
                             b[ni >> 1][(ni & 1) * 2], b[ni >> 1][(ni & 1) * 2 + 1]);
        }
    }
    __syncthreads();

    // Epilogue: bias + optional relu + tf32-round (next layer's A operand)
    const float* sbias = (const float*)(smem + 64);
    #pragma unroll
    for (int mi = 0; mi < 4; mi++) {
        const int r0 = m0 + wm * 64 + mi * 16 + (l >> 2);
        #pragma unroll
        for (int ni = 0; ni < 4; ni++) {
            const int ct = wn * 32 + ni * 8 + (l & 3) * 2;  // col within tile
            float b0 = sbias[ct], b1 = sbias[ct + 1];
            float v[4] = { acc[mi][ni][0] + b0, acc[mi][ni][1] + b1,
                           acc[mi][ni][2] + b0, acc[mi][ni][3] + b1 };
            if (relu_round) {
                #pragma unroll
                for (int j = 0; j < 4; j++) v[j] = to_tf32(fmaxf(v[j], 0.f));
            }
            const int n = n0 + ct;
            if (((ldc & 1) == 0) && (n + 1 < nvalid)) {
                *(float2*)(C + (size_t)r0 * ldc + n)       = make_float2(v[0], v[1]);
                *(float2*)(C + (size_t)(r0 + 8) * ldc + n) = make_float2(v[2], v[3]);
            } else {
                if (n < nvalid)     { C[(size_t)r0 * ldc + n]           = v[0];
                                      C[(size_t)(r0 + 8) * ldc + n]     = v[2]; }
                if (n + 1 < nvalid) { C[(size_t)r0 * ldc + n + 1]       = v[1];
                                      C[(size_t)(r0 + 8) * ldc + n + 1] = v[3]; }
            }
        }
    }
}

// ---------------------------------------------------------------------------
// Launch
// ---------------------------------------------------------------------------
extern "C" void kernel_launch(void* const* d_in, const int* in_sizes, int n_in,
                              void* d_out, int out_size) {
    const float* features = (const float*)d_in[0];
    (void)d_in[1];   // batch_indices: group->MLP->ungroup is an identity perm.
    const float* W1 = (const float*)d_in[2];
    const float* b1 = (const float*)d_in[3];
    const float* W2 = (const float*)d_in[4];
    const float* b2 = (const float*)d_in[5];
    const float* Wc = (const float*)d_in[6];
    const float* bc = (const float*)d_in[7];
    float* out = (float*)d_out;

    float *xr, *w1t, *w2t, *wct, *c1, *c2;
    cudaGetSymbolAddress((void**)&xr,  g_Xr);
    cudaGetSymbolAddress((void**)&w1t, g_W1T);
    cudaGetSymbolAddress((void**)&w2t, g_W2T);
    cudaGetSymbolAddress((void**)&wct, g_WcT);
    cudaGetSymbolAddress((void**)&c1,  g_C1);
    cudaGetSymbolAddress((void**)&c2,  g_C2);

    cudaFuncSetAttribute(gemm_tf32_kernel,
                         cudaFuncAttributeMaxDynamicSharedMemorySize, GEMM_SMEM);

    // 1) RNA-round the features to tf32
    {
        int n4 = N_ROWS * FEAT_DIM / 4;   // 6,422,528 — divisible by 4
        round_tf32_kernel<<<2048, 256>>>((const float4*)features,
                                         (float4*)xr, n4);
    }

    // 2) Transpose+round weights to K-major [N, K]
    dim3 tb(32, 8);
    transpose_round_kernel<<<dim3(FEAT_DIM / 32, HID / 32), tb>>>(W1, w1t, FEAT_DIM, HID, HID);
    transpose_round_kernel<<<dim3(HID / 32, HID / 32), tb>>>(W2, w2t, HID, HID, HID);
    transpose_round_kernel<<<dim3(HID / 32, NCLS_PAD / 32), tb>>>(Wc, wct, HID, NCLS, NCLS_PAD);

    // 3) Three TF32 GEMMs
    gemm_tf32_kernel<<<dim3(HID / NT, N_ROWS / MT), 256, GEMM_SMEM>>>(
        xr, w1t, b1, c1, FEAT_DIM, HID, HID, HID, 1);
    gemm_tf32_kernel<<<dim3(HID / NT, N_ROWS / MT), 256, GEMM_SMEM>>>(
        c1, w2t, b2, c2, HID, HID, HID, HID, 1);
    gemm_tf32_kernel<<<dim3(NCLS_PAD / NT, N_ROWS / MT), 256, GEMM_SMEM>>>(
        c2, wct, bc, out, HID, NCLS, NCLS, NCLS, 0);
}